// round 6
// baseline (speedup 1.0000x reference)
#include <cuda_runtime.h>
#include <cstdint>

// Shape fixed by the bench: B=4, H=16, S=2048, D=64
#define S_LEN 2048
#define D_DIM 64
#define BH    64
#define QT    128               // q rows per CTA (4 warps x 32 rows)
#define NQT   (S_LEN / QT)      // 16
#define NKC   (S_LEN / 64)      // 32 k-chunks of 64

// ---------------- mask tile classification (64x64 tiles) ----------------
__device__ unsigned char g_mask_flags[32 * 32]; // [qt64][kc]: 0 all-zero, 1 mixed, 2 all-nonzero

__global__ void mask_flag_kernel(const int* __restrict__ mask) {
    __shared__ int s_any_zero, s_any_nz;
    if (threadIdx.x == 0) { s_any_zero = 0; s_any_nz = 0; }
    __syncthreads();
    const int tile = blockIdx.x;
    const int qt = tile >> 5, kc = tile & 31;
    int a0 = 0, a1 = 0;
    for (int i = threadIdx.x; i < 64 * 64; i += blockDim.x) {
        int r = i >> 6, c = i & 63;
        int m = mask[(size_t)(qt * 64 + r) * S_LEN + kc * 64 + c];
        if (m == 0) a0 = 1; else a1 = 1;
    }
    if (a0) atomicOr(&s_any_zero, 1);
    if (a1) atomicOr(&s_any_nz, 1);
    __syncthreads();
    if (threadIdx.x == 0)
        g_mask_flags[tile] = (unsigned char)(s_any_zero ? (s_any_nz ? 1 : 0) : 2);
}

__device__ __forceinline__ unsigned f2tf32(float x) {
    unsigned u; asm("cvt.rna.tf32.f32 %0, %1;" : "=r"(u) : "f"(x)); return u;
}

__device__ __forceinline__ void mma_tf32(float* c, const unsigned* a,
                                         unsigned b0, unsigned b1) {
    asm volatile(
        "mma.sync.aligned.m16n8k8.row.col.f32.tf32.tf32.f32 "
        "{%0,%1,%2,%3}, {%4,%5,%6,%7}, {%8,%9}, {%0,%1,%2,%3};"
        : "+f"(c[0]), "+f"(c[1]), "+f"(c[2]), "+f"(c[3])
        : "r"(a[0]), "r"(a[1]), "r"(a[2]), "r"(a[3]), "r"(b0), "r"(b1));
}

__device__ __forceinline__ void cp16(uint32_t dst, const float* src) {
    asm volatile("cp.async.cg.shared.global [%0], [%1], 16;" :: "r"(dst), "l"(src));
}
#define CP_COMMIT() asm volatile("cp.async.commit_group;" ::: "memory")
#define CP_WAIT1()  asm volatile("cp.async.wait_group 1;" ::: "memory")
#define CP_WAIT0()  asm volatile("cp.async.wait_group 0;" ::: "memory")

// Smem layout (floats). Strides for conflict-free fragment LDS:
//   stride 68 (mod32=4): bank = 4g+tig pattern; stride 72 (mod32=8): bank = 8tig+g.
// All row starts stay 16B-aligned (272B, 288B row pitches) for cp.async.
#define SKS 68
#define SVS 72
#define SPS 68
#define OFF_K0 0
#define OFF_K1 (64 * SKS)                 // 4352
#define OFF_V0 (2 * 64 * SKS)             // 8704
#define OFF_V1 (2 * 64 * SKS + 64 * SVS)  // 13312
#define OFF_P  (2 * 64 * SKS + 2 * 64 * SVS) // 17920
#define SMEM_FLOATS (OFF_P + 128 * SPS)   // 26624 floats = 106496 B

// m16n8k8 frag mapping: A a0(g,c) a1(g+8,c) a2(g,c+4) a3(g+8,c+4), g=lane>>2, c=lane&3
//                       B b0(row=c,col=g) b1(row=c+4,col=g)
//                       C c0(g,2c) c1(g,2c+1) c2(g+8,2c) c3(g+8,2c+1)
__global__ __launch_bounds__(128)
void fused_attn3_kernel(const float* __restrict__ q, const float* __restrict__ k,
                        const float* __restrict__ v, const int* __restrict__ mask,
                        float* __restrict__ out, float* __restrict__ attn,
                        int has_attn)
{
    extern __shared__ float sm[];
    float* sP = sm + OFF_P;    // [128][68] P tile (tf32 bits)

    const int tid = threadIdx.x;
    const int warp = tid >> 5, lane = tid & 31;
    const int g = lane >> 2, tig = lane & 3;
    const int qtile = blockIdx.x, bh = blockIdx.y;
    const int wrow = warp * 32;
    const size_t bh_qkv = (size_t)bh * S_LEN * D_DIM;
    const int gq = qtile * QT + wrow;          // warp's first global q row
    const uint32_t sbu = (uint32_t)__cvta_generic_to_shared(sm);

    const float* kbase = k + bh_qkv;
    const float* vbase = v + bh_qkv;

    // ---- Q a-fragments in registers (scaled by 1/8, RNA tf32); 2 m-tiles ----
    unsigned aq[2][8][4];
    {
        const float* qp = q + bh_qkv + (size_t)gq * D_DIM;
        #pragma unroll
        for (int t = 0; t < 2; ++t)
            #pragma unroll
            for (int kt = 0; kt < 8; ++kt) {
                const float* r0 = qp + (size_t)(t * 16 + g) * D_DIM + kt * 8;
                const float* r1 = r0 + 8 * D_DIM;
                aq[t][kt][0] = f2tf32(r0[tig]     * 0.125f);
                aq[t][kt][1] = f2tf32(r1[tig]     * 0.125f);
                aq[t][kt][2] = f2tf32(r0[tig + 4] * 0.125f);
                aq[t][kt][3] = f2tf32(r1[tig + 4] * 0.125f);
            }
    }

    const int fb0 = (qtile * 2) * 32, fb1 = (qtile * 2 + 1) * 32;

    // async fill helpers (raw fp32 into smem; tf32 cvt happens at consume time)
    auto fillK = [&](int buf, int kc) {
        const float* kp = kbase + (size_t)kc * 64 * D_DIM;
        const uint32_t base = sbu + (buf ? OFF_K1 : OFF_K0) * 4;
        #pragma unroll
        for (int i = 0; i < 8; ++i) {
            int j = tid + i * 128;
            int r = j >> 4, c4 = (j & 15) << 2;
            cp16(base + (uint32_t)(r * SKS + c4) * 4, kp + r * D_DIM + c4);
        }
    };
    auto fillV = [&](int buf, int kc) {
        const float* vp = vbase + (size_t)kc * 64 * D_DIM;
        const uint32_t base = sbu + (buf ? OFF_V1 : OFF_V0) * 4;
        #pragma unroll
        for (int i = 0; i < 8; ++i) {
            int j = tid + i * 128;
            int r = j >> 4, c4 = (j & 15) << 2;
            cp16(base + (uint32_t)(r * SVS + c4) * 4, vp + r * D_DIM + c4);
        }
    };

    // ================= Pass 1: row sums l = sum exp(|s| masked) =================
    float l00 = 0.f, l01 = 0.f, l10 = 0.f, l11 = 0.f;
    {
        int buf = 0;
        fillK(0, 0);
        CP_COMMIT();
        for (int kc = 0; kc < NKC; ++kc) {
            if (kc + 1 < NKC) { fillK(buf ^ 1, kc + 1); CP_COMMIT(); CP_WAIT1(); }
            else              { CP_WAIT0(); }
            __syncthreads();

            const float* sKb = sm + (buf ? OFF_K1 : OFF_K0);
            const int cf0 = g_mask_flags[fb0 + kc], cf1 = g_mask_flags[fb1 + kc];
            const int wflag = (warp < 2) ? cf0 : cf1;

            #pragma unroll
            for (int nt = 0; nt < 8; ++nt) {
                float C0[4] = {0.f, 0.f, 0.f, 0.f}, C1[4] = {0.f, 0.f, 0.f, 0.f};
                #pragma unroll
                for (int kt = 0; kt < 8; ++kt) {
                    unsigned b0 = f2tf32(sKb[(nt * 8 + g) * SKS + kt * 8 + tig]);
                    unsigned b1 = f2tf32(sKb[(nt * 8 + g) * SKS + kt * 8 + tig + 4]);
                    mma_tf32(C0, aq[0][kt], b0, b1);
                    mma_tf32(C1, aq[1][kt], b0, b1);
                }
                if (wflag == 2) {
                    l00 += __expf(fabsf(C0[0])) + __expf(fabsf(C0[1]));
                    l01 += __expf(fabsf(C0[2])) + __expf(fabsf(C0[3]));
                    l10 += __expf(fabsf(C1[0])) + __expf(fabsf(C1[1]));
                    l11 += __expf(fabsf(C1[2])) + __expf(fabsf(C1[3]));
                } else {
                    const int colm = kc * 64 + nt * 8 + 2 * tig;
                    int2 mA = *(const int2*)(mask + (size_t)(gq + g)      * S_LEN + colm);
                    int2 mB = *(const int2*)(mask + (size_t)(gq + g + 8)  * S_LEN + colm);
                    int2 mC = *(const int2*)(mask + (size_t)(gq + g + 16) * S_LEN + colm);
                    int2 mD = *(const int2*)(mask + (size_t)(gq + g + 24) * S_LEN + colm);
                    if (mA.x) l00 += __expf(fabsf(C0[0]));
                    if (mA.y) l00 += __expf(fabsf(C0[1]));
                    if (mB.x) l01 += __expf(fabsf(C0[2]));
                    if (mB.y) l01 += __expf(fabsf(C0[3]));
                    if (mC.x) l10 += __expf(fabsf(C1[0]));
                    if (mC.y) l10 += __expf(fabsf(C1[1]));
                    if (mD.x) l11 += __expf(fabsf(C1[2]));
                    if (mD.y) l11 += __expf(fabsf(C1[3]));
                }
            }
            __syncthreads();   // all warps done reading this buffer before refill
            buf ^= 1;
        }
    }
    // quad reduce over tig (lanes with same g share rows)
    l00 += __shfl_xor_sync(0xffffffffu, l00, 1); l00 += __shfl_xor_sync(0xffffffffu, l00, 2);
    l01 += __shfl_xor_sync(0xffffffffu, l01, 1); l01 += __shfl_xor_sync(0xffffffffu, l01, 2);
    l10 += __shfl_xor_sync(0xffffffffu, l10, 1); l10 += __shfl_xor_sync(0xffffffffu, l10, 2);
    l11 += __shfl_xor_sync(0xffffffffu, l11, 1); l11 += __shfl_xor_sync(0xffffffffu, l11, 2);
    const float il00 = 1.f / l00, il01 = 1.f / l01;
    const float il10 = 1.f / l10, il11 = 1.f / l11;

    // ================= Pass 2: attn write + O = P @ V =================
    float O0[8][4], O1[8][4];
    #pragma unroll
    for (int nt = 0; nt < 8; ++nt)
        #pragma unroll
        for (int i = 0; i < 4; ++i) { O0[nt][i] = 0.f; O1[nt][i] = 0.f; }

    const size_t abase = (size_t)bh * S_LEN * S_LEN + (size_t)(qtile * QT) * S_LEN;

    {
        int buf = 0;
        fillK(0, 0); fillV(0, 0);
        CP_COMMIT();
        for (int kc = 0; kc < NKC; ++kc) {
            if (kc + 1 < NKC) { fillK(buf ^ 1, kc + 1); fillV(buf ^ 1, kc + 1);
                                CP_COMMIT(); CP_WAIT1(); }
            else              { CP_WAIT0(); }
            __syncthreads();

            const float* sKb = sm + (buf ? OFF_K1 : OFF_K0);
            const float* sVb = sm + (buf ? OFF_V1 : OFF_V0);
            const int cf0 = g_mask_flags[fb0 + kc], cf1 = g_mask_flags[fb1 + kc];
            const int wflag = (warp < 2) ? cf0 : cf1;

            // ---- QK^T + fused epilogue, per n-tile (keeps C live-range tiny) ----
            #pragma unroll
            for (int nt = 0; nt < 8; ++nt) {
                float C0[4] = {0.f, 0.f, 0.f, 0.f}, C1[4] = {0.f, 0.f, 0.f, 0.f};
                #pragma unroll
                for (int kt = 0; kt < 8; ++kt) {
                    unsigned b0 = f2tf32(sKb[(nt * 8 + g) * SKS + kt * 8 + tig]);
                    unsigned b1 = f2tf32(sKb[(nt * 8 + g) * SKS + kt * 8 + tig + 4]);
                    mma_tf32(C0, aq[0][kt], b0, b1);
                    mma_tf32(C1, aq[1][kt], b0, b1);
                }
                #pragma unroll
                for (int t = 0; t < 2; ++t) {
                    const float* C = t ? C1 : C0;
                    const float ilA = t ? il10 : il00, ilB = t ? il11 : il01;
                    const int r0 = wrow + t * 16 + g, r1 = r0 + 8;
                    float p0, p1, p2, p3;
                    if (wflag == 2) {
                        p0 = __expf(fabsf(C[0])) * ilA;
                        p1 = __expf(fabsf(C[1])) * ilA;
                        p2 = __expf(fabsf(C[2])) * ilB;
                        p3 = __expf(fabsf(C[3])) * ilB;
                    } else {
                        int colm = kc * 64 + nt * 8 + 2 * tig;
                        int2 m0 = *(const int2*)(mask + (size_t)(qtile * QT + r0) * S_LEN + colm);
                        int2 m1 = *(const int2*)(mask + (size_t)(qtile * QT + r1) * S_LEN + colm);
                        p0 = m0.x ? __expf(fabsf(C[0])) * ilA : 0.f;
                        p1 = m0.y ? __expf(fabsf(C[1])) * ilA : 0.f;
                        p2 = m1.x ? __expf(fabsf(C[2])) * ilB : 0.f;
                        p3 = m1.y ? __expf(fabsf(C[3])) * ilB : 0.f;
                    }
                    const int colb = nt * 8 + 2 * tig;
                    if (has_attn) {   // streaming stores: don't pollute L2 (K/V reuse lives there)
                        __stcs((float2*)(attn + abase + (size_t)r0 * S_LEN + kc * 64 + colb),
                               make_float2(p0, p1));
                        __stcs((float2*)(attn + abase + (size_t)r1 * S_LEN + kc * 64 + colb),
                               make_float2(p2, p3));
                    }
                    *(float2*)(&sP[r0 * SPS + colb]) = make_float2(
                        __uint_as_float(f2tf32(p0)), __uint_as_float(f2tf32(p1)));
                    *(float2*)(&sP[r1 * SPS + colb]) = make_float2(
                        __uint_as_float(f2tf32(p2)), __uint_as_float(f2tf32(p3)));
                }
            }
            __syncwarp();   // sP rows are warp-private: write->read within warp only

            // ---- O += P @ V ----
            #pragma unroll
            for (int kt = 0; kt < 8; ++kt) {
                unsigned pa0[4], pa1[4];
                pa0[0] = __float_as_uint(sP[(wrow + g)      * SPS + kt * 8 + tig]);
                pa0[1] = __float_as_uint(sP[(wrow + g + 8)  * SPS + kt * 8 + tig]);
                pa0[2] = __float_as_uint(sP[(wrow + g)      * SPS + kt * 8 + tig + 4]);
                pa0[3] = __float_as_uint(sP[(wrow + g + 8)  * SPS + kt * 8 + tig + 4]);
                pa1[0] = __float_as_uint(sP[(wrow + g + 16) * SPS + kt * 8 + tig]);
                pa1[1] = __float_as_uint(sP[(wrow + g + 24) * SPS + kt * 8 + tig]);
                pa1[2] = __float_as_uint(sP[(wrow + g + 16) * SPS + kt * 8 + tig + 4]);
                pa1[3] = __float_as_uint(sP[(wrow + g + 24) * SPS + kt * 8 + tig + 4]);
                #pragma unroll
                for (int nt = 0; nt < 8; ++nt) {
                    unsigned b0 = f2tf32(sVb[(kt * 8 + tig)     * SVS + nt * 8 + g]);
                    unsigned b1 = f2tf32(sVb[(kt * 8 + tig + 4) * SVS + nt * 8 + g]);
                    mma_tf32(O0[nt], pa0, b0, b1);
                    mma_tf32(O1[nt], pa1, b0, b1);
                }
            }
            __syncthreads();   // buffer fully consumed before next refill
            buf ^= 1;
        }
    }

    // ================= Output store =================
    #pragma unroll
    for (int t = 0; t < 2; ++t) {
        float (*O)[4] = t ? O1 : O0;
        const int r0 = gq + t * 16 + g;
        float* o0 = out + bh_qkv + (size_t)r0 * D_DIM;
        float* o1 = out + bh_qkv + (size_t)(r0 + 8) * D_DIM;
        #pragma unroll
        for (int nt = 0; nt < 8; ++nt) {
            *(float2*)(o0 + nt * 8 + 2 * tig) = make_float2(O[nt][0], O[nt][1]);
            *(float2*)(o1 + nt * 8 + 2 * tig) = make_float2(O[nt][2], O[nt][3]);
        }
    }
}

extern "C" void kernel_launch(void* const* d_in, const int* in_sizes, int n_in,
                              void* d_out, int out_size) {
    const float* q    = (const float*)d_in[0];
    const float* k    = (const float*)d_in[1];
    const float* v    = (const float*)d_in[2];
    const int*   mask = (const int*)d_in[3];

    float* out = (float*)d_out;
    const long long outN  = (long long)BH * S_LEN * D_DIM;   // 8,388,608
    const long long attnN = (long long)BH * S_LEN * S_LEN;   // 268,435,456
    float* attn = nullptr;
    int has_attn = 0;
    if ((long long)out_size >= outN + attnN) {
        attn = out + outN;
        has_attn = 1;
    }

    static int configured = 0;
    if (!configured) {
        cudaFuncSetAttribute(fused_attn3_kernel,
                             cudaFuncAttributeMaxDynamicSharedMemorySize,
                             SMEM_FLOATS * 4);
        configured = 1;
    }

    mask_flag_kernel<<<32 * 32, 256>>>(mask);
    dim3 grid(NQT, BH);
    fused_attn3_kernel<<<grid, 128, SMEM_FLOATS * 4>>>(q, k, v, mask, out, attn, has_attn);
}

// round 8
// speedup vs baseline: 1.6917x; 1.6917x over previous
#include <cuda_runtime.h>
#include <cuda_fp16.h>
#include <cstdint>

// Shape fixed by the bench: B=4, H=16, S=2048, D=64
#define S_LEN 2048
#define D_DIM 64
#define BH    64
#define QT    128               // q rows per CTA (4 warps x 32 rows, 2 m-tiles each)
#define NQT   (S_LEN / QT)      // 16
#define NKC   (S_LEN / 64)      // 32 k-chunks of 64

// ---------------- mask tile classification (64x64 tiles) ----------------
__device__ unsigned char g_mask_flags[32 * 32]; // [qt64][kc]: 0 all-zero, 1 mixed, 2 all-nonzero

__global__ void mask_flag_kernel(const int* __restrict__ mask) {
    __shared__ int s_any_zero, s_any_nz;
    if (threadIdx.x == 0) { s_any_zero = 0; s_any_nz = 0; }
    __syncthreads();
    const int tile = blockIdx.x;
    const int qt = tile >> 5, kc = tile & 31;
    int a0 = 0, a1 = 0;
    for (int i = threadIdx.x; i < 64 * 64; i += blockDim.x) {
        int r = i >> 6, c = i & 63;
        int m = mask[(size_t)(qt * 64 + r) * S_LEN + kc * 64 + c];
        if (m == 0) a0 = 1; else a1 = 1;
    }
    if (a0) atomicOr(&s_any_zero, 1);
    if (a1) atomicOr(&s_any_nz, 1);
    __syncthreads();
    if (threadIdx.x == 0)
        g_mask_flags[tile] = (unsigned char)(s_any_zero ? (s_any_nz ? 1 : 0) : 2);
}

// Pack two fp32 -> one f16x2 register (x -> low half, y -> high half)
__device__ __forceinline__ unsigned packh2(float x, float y) {
    unsigned u;
    asm("cvt.rn.f16x2.f32 %0, %1, %2;" : "=r"(u) : "f"(y), "f"(x));
    return u;
}

// m16n8k16 fp16 MMA, fp32 accum.
// A: a0=(g,2c..2c+1) a1=(g+8,..) a2=(g,2c+8..9) a3=(g+8,..)   g=lane>>2, c=lane&3
// B: b0=(k=2c..2c+1, n=g)  b1=(k=2c+8..9, n=g)
// C: c0=(g,2c) c1=(g,2c+1) c2=(g+8,2c) c3=(g+8,2c+1)
__device__ __forceinline__ void mma_f16(float* c, const unsigned* a,
                                        unsigned b0, unsigned b1) {
    asm volatile(
        "mma.sync.aligned.m16n8k16.row.col.f32.f16.f16.f32 "
        "{%0,%1,%2,%3}, {%4,%5,%6,%7}, {%8,%9}, {%0,%1,%2,%3};"
        : "+f"(c[0]), "+f"(c[1]), "+f"(c[2]), "+f"(c[3])
        : "r"(a[0]), "r"(a[1]), "r"(a[2]), "r"(a[3]), "r"(b0), "r"(b1));
}

__device__ __forceinline__ void ldmx4t(unsigned& r0, unsigned& r1,
                                       unsigned& r2, unsigned& r3, unsigned addr) {
    asm volatile("ldmatrix.sync.aligned.m8n8.x4.trans.shared.b16 {%0,%1,%2,%3}, [%4];"
                 : "=r"(r0), "=r"(r1), "=r"(r2), "=r"(r3) : "r"(addr));
}

// Smem (halves). Row stride 72 halves = 36 words == 4 (mod 32):
//  .b32 frag loads  -> bank 4g+tig (conflict-free)
//  ldmatrix rows    -> word offsets 4r, tile perfectly covers 32 banks
#define STH 72
__global__ __launch_bounds__(128, 3)
void fused_attn4_kernel(const float* __restrict__ q, const float* __restrict__ k,
                        const float* __restrict__ v, const int* __restrict__ mask,
                        float* __restrict__ out, float* __restrict__ attn,
                        int has_attn)
{
    __shared__ __half sK[64 * STH];
    __shared__ __half sV[64 * STH];
    __shared__ __half sP[128 * STH];

    const int tid = threadIdx.x;
    const int warp = tid >> 5, lane = tid & 31;
    const int g = lane >> 2, tig = lane & 3;
    const int qtile = blockIdx.x, bh = blockIdx.y;
    const int wrow = warp * 32;
    const size_t bh_qkv = (size_t)bh * S_LEN * D_DIM;
    const int gq = qtile * QT + wrow;          // warp's first global q row

    const float* kbase = k + bh_qkv;
    const float* vbase = v + bh_qkv;

    // ---- Q a-fragments (fp16, scaled by 1/8); 2 m-tiles x 4 k-tiles ----
    unsigned aq[2][4][4];
    {
        const float* qp = q + bh_qkv + (size_t)gq * D_DIM;
        #pragma unroll
        for (int t = 0; t < 2; ++t)
            #pragma unroll
            for (int kt = 0; kt < 4; ++kt) {
                const float* r0 = qp + (size_t)(t * 16 + g) * D_DIM + kt * 16 + 2 * tig;
                const float* r1 = r0 + 8 * D_DIM;
                float2 x0 = *(const float2*)(r0);
                float2 x1 = *(const float2*)(r1);
                float2 x2 = *(const float2*)(r0 + 8);
                float2 x3 = *(const float2*)(r1 + 8);
                aq[t][kt][0] = packh2(x0.x * 0.125f, x0.y * 0.125f);
                aq[t][kt][1] = packh2(x1.x * 0.125f, x1.y * 0.125f);
                aq[t][kt][2] = packh2(x2.x * 0.125f, x2.y * 0.125f);
                aq[t][kt][3] = packh2(x3.x * 0.125f, x3.y * 0.125f);
            }
    }

    const int fb0 = (qtile * 2) * 32, fb1 = (qtile * 2 + 1) * 32;

    // ================= Pass 1: row sums l = sum exp(|s| masked) =================
    float l00 = 0.f, l01 = 0.f, l10 = 0.f, l11 = 0.f;
    for (int kc = 0; kc < NKC; ++kc) {
        const int cf0 = g_mask_flags[fb0 + kc], cf1 = g_mask_flags[fb1 + kc];
        if (cf0 == 0 && cf1 == 0) continue;
        __syncthreads();
        {   // K chunk fill: fp32 -> fp16, row-major stride 72
            const float* kp = kbase + (size_t)kc * 64 * D_DIM;
            #pragma unroll
            for (int i = 0; i < 8; ++i) {
                int j = tid + i * 128;
                int r = j >> 4, c4 = (j & 15) << 2;
                float4 val = *(const float4*)(kp + (size_t)r * D_DIM + c4);
                *(uint2*)(&sK[r * STH + c4]) =
                    make_uint2(packh2(val.x, val.y), packh2(val.z, val.w));
            }
        }
        __syncthreads();

        const int wflag = (warp < 2) ? cf0 : cf1;
        #pragma unroll
        for (int nt = 0; nt < 8; ++nt) {
            float C0[4] = {0.f, 0.f, 0.f, 0.f}, C1[4] = {0.f, 0.f, 0.f, 0.f};
            #pragma unroll
            for (int kt = 0; kt < 4; ++kt) {
                unsigned b0 = *(const unsigned*)(&sK[(nt * 8 + g) * STH + kt * 16 + 2 * tig]);
                unsigned b1 = *(const unsigned*)(&sK[(nt * 8 + g) * STH + kt * 16 + 2 * tig + 8]);
                mma_f16(C0, aq[0][kt], b0, b1);
                mma_f16(C1, aq[1][kt], b0, b1);
            }
            if (wflag == 2) {
                l00 += __expf(fabsf(C0[0])) + __expf(fabsf(C0[1]));
                l01 += __expf(fabsf(C0[2])) + __expf(fabsf(C0[3]));
                l10 += __expf(fabsf(C1[0])) + __expf(fabsf(C1[1]));
                l11 += __expf(fabsf(C1[2])) + __expf(fabsf(C1[3]));
            } else {
                const int colm = kc * 64 + nt * 8 + 2 * tig;
                int2 mA = *(const int2*)(mask + (size_t)(gq + g)      * S_LEN + colm);
                int2 mB = *(const int2*)(mask + (size_t)(gq + g + 8)  * S_LEN + colm);
                int2 mC = *(const int2*)(mask + (size_t)(gq + g + 16) * S_LEN + colm);
                int2 mD = *(const int2*)(mask + (size_t)(gq + g + 24) * S_LEN + colm);
                if (mA.x) l00 += __expf(fabsf(C0[0]));
                if (mA.y) l00 += __expf(fabsf(C0[1]));
                if (mB.x) l01 += __expf(fabsf(C0[2]));
                if (mB.y) l01 += __expf(fabsf(C0[3]));
                if (mC.x) l10 += __expf(fabsf(C1[0]));
                if (mC.y) l10 += __expf(fabsf(C1[1]));
                if (mD.x) l11 += __expf(fabsf(C1[2]));
                if (mD.y) l11 += __expf(fabsf(C1[3]));
            }
        }
    }
    // quad reduce over tig (lanes with same g share rows)
    l00 += __shfl_xor_sync(0xffffffffu, l00, 1); l00 += __shfl_xor_sync(0xffffffffu, l00, 2);
    l01 += __shfl_xor_sync(0xffffffffu, l01, 1); l01 += __shfl_xor_sync(0xffffffffu, l01, 2);
    l10 += __shfl_xor_sync(0xffffffffu, l10, 1); l10 += __shfl_xor_sync(0xffffffffu, l10, 2);
    l11 += __shfl_xor_sync(0xffffffffu, l11, 1); l11 += __shfl_xor_sync(0xffffffffu, l11, 2);
    const float il00 = 1.f / l00, il01 = 1.f / l01;
    const float il10 = 1.f / l10, il11 = 1.f / l11;

    // ================= Pass 2: attn write + O = P @ V =================
    float O0[8][4], O1[8][4];
    #pragma unroll
    for (int nt = 0; nt < 8; ++nt)
        #pragma unroll
        for (int i = 0; i < 4; ++i) { O0[nt][i] = 0.f; O1[nt][i] = 0.f; }

    const size_t abase = (size_t)bh * S_LEN * S_LEN + (size_t)(qtile * QT) * S_LEN;
    const unsigned svb = (unsigned)__cvta_generic_to_shared(sV);

    for (int kc = 0; kc < NKC; ++kc) {
        const int cf0 = g_mask_flags[fb0 + kc], cf1 = g_mask_flags[fb1 + kc];
        if (cf0 == 0 && cf1 == 0) {
            if (has_attn) {
                float4 z = make_float4(0.f, 0.f, 0.f, 0.f);
                for (int j = tid; j < 2048; j += 128) {
                    int r = j >> 4, c4 = (j & 15) << 2;
                    *(float4*)(attn + abase + (size_t)r * S_LEN + kc * 64 + c4) = z;
                }
            }
            continue;
        }
        __syncthreads();
        {   // K + V chunk fills (both row-major fp16, stride 72)
            const float* kp = kbase + (size_t)kc * 64 * D_DIM;
            const float* vp = vbase + (size_t)kc * 64 * D_DIM;
            #pragma unroll
            for (int i = 0; i < 8; ++i) {
                int j = tid + i * 128;
                int r = j >> 4, c4 = (j & 15) << 2;
                float4 kv = *(const float4*)(kp + (size_t)r * D_DIM + c4);
                *(uint2*)(&sK[r * STH + c4]) =
                    make_uint2(packh2(kv.x, kv.y), packh2(kv.z, kv.w));
                float4 vv = *(const float4*)(vp + (size_t)r * D_DIM + c4);
                *(uint2*)(&sV[r * STH + c4]) =
                    make_uint2(packh2(vv.x, vv.y), packh2(vv.z, vv.w));
            }
        }
        __syncthreads();

        const int wflag = (warp < 2) ? cf0 : cf1;

        // ---- QK^T + fused epilogue per n-tile ----
        #pragma unroll
        for (int nt = 0; nt < 8; ++nt) {
            float C0[4] = {0.f, 0.f, 0.f, 0.f}, C1[4] = {0.f, 0.f, 0.f, 0.f};
            #pragma unroll
            for (int kt = 0; kt < 4; ++kt) {
                unsigned b0 = *(const unsigned*)(&sK[(nt * 8 + g) * STH + kt * 16 + 2 * tig]);
                unsigned b1 = *(const unsigned*)(&sK[(nt * 8 + g) * STH + kt * 16 + 2 * tig + 8]);
                mma_f16(C0, aq[0][kt], b0, b1);
                mma_f16(C1, aq[1][kt], b0, b1);
            }
            #pragma unroll
            for (int t = 0; t < 2; ++t) {
                const float* C = t ? C1 : C0;
                const float ilA = t ? il10 : il00, ilB = t ? il11 : il01;
                const int r0 = wrow + t * 16 + g, r1 = r0 + 8;
                float p0, p1, p2, p3;
                if (wflag == 2) {
                    p0 = __expf(fabsf(C[0])) * ilA;
                    p1 = __expf(fabsf(C[1])) * ilA;
                    p2 = __expf(fabsf(C[2])) * ilB;
                    p3 = __expf(fabsf(C[3])) * ilB;
                } else {
                    int colm = kc * 64 + nt * 8 + 2 * tig;
                    int2 m0 = *(const int2*)(mask + (size_t)(qtile * QT + r0) * S_LEN + colm);
                    int2 m1 = *(const int2*)(mask + (size_t)(qtile * QT + r1) * S_LEN + colm);
                    p0 = m0.x ? __expf(fabsf(C[0])) * ilA : 0.f;
                    p1 = m0.y ? __expf(fabsf(C[1])) * ilA : 0.f;
                    p2 = m1.x ? __expf(fabsf(C[2])) * ilB : 0.f;
                    p3 = m1.y ? __expf(fabsf(C[3])) * ilB : 0.f;
                }
                const int colb = nt * 8 + 2 * tig;
                if (has_attn) {   // streaming: keep K/V reuse in L2
                    __stcs((float2*)(attn + abase + (size_t)r0 * S_LEN + kc * 64 + colb),
                           make_float2(p0, p1));
                    __stcs((float2*)(attn + abase + (size_t)r1 * S_LEN + kc * 64 + colb),
                           make_float2(p2, p3));
                }
                *(unsigned*)(&sP[r0 * STH + colb]) = packh2(p0, p1);
                *(unsigned*)(&sP[r1 * STH + colb]) = packh2(p2, p3);
            }
        }
        __syncwarp();   // sP rows are warp-private (write->read within warp)

        // ---- O += P @ V  (a from sP packed pairs; b via ldmatrix.x4.trans) ----
        #pragma unroll
        for (int kt = 0; kt < 4; ++kt) {
            unsigned pa0[4], pa1[4];
            {
                const int cA = kt * 16 + 2 * tig, cB = cA + 8;
                pa0[0] = *(const unsigned*)(&sP[(wrow + g)      * STH + cA]);
                pa0[1] = *(const unsigned*)(&sP[(wrow + g + 8)  * STH + cA]);
                pa0[2] = *(const unsigned*)(&sP[(wrow + g)      * STH + cB]);
                pa0[3] = *(const unsigned*)(&sP[(wrow + g + 8)  * STH + cB]);
                pa1[0] = *(const unsigned*)(&sP[(wrow + g + 16) * STH + cA]);
                pa1[1] = *(const unsigned*)(&sP[(wrow + g + 24) * STH + cA]);
                pa1[2] = *(const unsigned*)(&sP[(wrow + g + 16) * STH + cB]);
                pa1[3] = *(const unsigned*)(&sP[(wrow + g + 24) * STH + cB]);
            }
            #pragma unroll
            for (int p = 0; p < 4; ++p) {
                // 4 transposed 8x8 tiles: rows k = kt*16 + (lane>>3 &1)*8 + (lane&7),
                // cols n = p*16 + (lane>>4)*8  -> b0,b1 for nt=2p; b2,b3 for nt=2p+1
                const int vrow = kt * 16 + ((lane >> 3) & 1) * 8 + (lane & 7);
                const int vcol = p * 16 + (lane >> 4) * 8;
                unsigned b0, b1, b2, b3;
                ldmx4t(b0, b1, b2, b3, svb + (unsigned)(vrow * STH + vcol) * 2);
                mma_f16(O0[2 * p],     pa0, b0, b1);
                mma_f16(O0[2 * p + 1], pa0, b2, b3);
                mma_f16(O1[2 * p],     pa1, b0, b1);
                mma_f16(O1[2 * p + 1], pa1, b2, b3);
            }
        }
    }

    // ================= Output store =================
    #pragma unroll
    for (int t = 0; t < 2; ++t) {
        float (*O)[4] = t ? O1 : O0;
        const int r0 = gq + t * 16 + g;
        float* o0 = out + bh_qkv + (size_t)r0 * D_DIM;
        float* o1 = out + bh_qkv + (size_t)(r0 + 8) * D_DIM;
        #pragma unroll
        for (int nt = 0; nt < 8; ++nt) {
            *(float2*)(o0 + nt * 8 + 2 * tig) = make_float2(O[nt][0], O[nt][1]);
            *(float2*)(o1 + nt * 8 + 2 * tig) = make_float2(O[nt][2], O[nt][3]);
        }
    }
}

extern "C" void kernel_launch(void* const* d_in, const int* in_sizes, int n_in,
                              void* d_out, int out_size) {
    const float* q    = (const float*)d_in[0];
    const float* k    = (const float*)d_in[1];
    const float* v    = (const float*)d_in[2];
    const int*   mask = (const int*)d_in[3];

    float* out = (float*)d_out;
    const long long outN  = (long long)BH * S_LEN * D_DIM;   // 8,388,608
    const long long attnN = (long long)BH * S_LEN * S_LEN;   // 268,435,456
    float* attn = nullptr;
    int has_attn = 0;
    if ((long long)out_size >= outN + attnN) {
        attn = out + outN;
        has_attn = 1;
    }

    mask_flag_kernel<<<32 * 32, 256>>>(mask);
    dim3 grid(NQT, BH);
    fused_attn4_kernel<<<grid, 128>>>(q, k, v, mask, out, attn, has_attn);
}